// round 3
// baseline (speedup 1.0000x reference)
#include <cuda_runtime.h>
#include <math.h>

#define DD   1024
#define NE   100
#define BT   32768   // 8*4096

// ---------------- device scratch ----------------
__device__ float g_cnorm[128 * DD];             // normalized centroids, zero-padded to 128 rows
__device__ float g_apad[(size_t)BT * 128];      // assignment, padded to 128 entities
__device__ float g_wpart[256 * 128];            // per-block weight partials
__device__ float g_weights[8 * 128];            // sum over T + 1e-6
__device__ float g_efpart[(size_t)4 * 8 * 128 * DD]; // split-K partials for GEMM2

// ---------------- packed fp32x2 helpers (sm_103a) ----------------
__device__ __forceinline__ unsigned long long pk2(float lo, float hi) {
    unsigned long long r;
    asm("mov.b64 %0, {%1, %2};" : "=l"(r) : "f"(lo), "f"(hi));
    return r;
}
__device__ __forceinline__ void fma2(unsigned long long& d, unsigned long long a, unsigned long long b) {
    asm("fma.rn.f32x2 %0, %1, %2, %0;" : "+l"(d) : "l"(a), "l"(b));
}
__device__ __forceinline__ float2 upk(unsigned long long v) {
    float2 r;
    asm("mov.b64 {%0, %1}, %2;" : "=f"(r.x), "=f"(r.y) : "l"(v));
    return r;
}

// 16-step K inner product. US: broadcast side rows ty*8..+7. VS: pair side cols tx*4.. and 64+tx*4..
#define INNER16(US, VS)                                                                             \
    _Pragma("unroll")                                                                               \
    for (int kk = 0; kk < 16; ++kk) {                                                               \
        float4 u0 = *(const float4*)&US[kk][ty * 8];                                                \
        float4 u1 = *(const float4*)&US[kk][ty * 8 + 4];                                            \
        float4 v0 = *(const float4*)&VS[kk][tx * 4];                                                \
        float4 v1 = *(const float4*)&VS[kk][64 + tx * 4];                                           \
        unsigned long long vp0 = pk2(v0.x, v0.y), vp1 = pk2(v0.z, v0.w);                            \
        unsigned long long vp2 = pk2(v1.x, v1.y), vp3 = pk2(v1.z, v1.w);                            \
        unsigned long long ud;                                                                      \
        ud = pk2(u0.x, u0.x); fma2(acc[0][0], ud, vp0); fma2(acc[0][1], ud, vp1);                   \
                              fma2(acc[0][2], ud, vp2); fma2(acc[0][3], ud, vp3);                   \
        ud = pk2(u0.y, u0.y); fma2(acc[1][0], ud, vp0); fma2(acc[1][1], ud, vp1);                   \
                              fma2(acc[1][2], ud, vp2); fma2(acc[1][3], ud, vp3);                   \
        ud = pk2(u0.z, u0.z); fma2(acc[2][0], ud, vp0); fma2(acc[2][1], ud, vp1);                   \
                              fma2(acc[2][2], ud, vp2); fma2(acc[2][3], ud, vp3);                   \
        ud = pk2(u0.w, u0.w); fma2(acc[3][0], ud, vp0); fma2(acc[3][1], ud, vp1);                   \
                              fma2(acc[3][2], ud, vp2); fma2(acc[3][3], ud, vp3);                   \
        ud = pk2(u1.x, u1.x); fma2(acc[4][0], ud, vp0); fma2(acc[4][1], ud, vp1);                   \
                              fma2(acc[4][2], ud, vp2); fma2(acc[4][3], ud, vp3);                   \
        ud = pk2(u1.y, u1.y); fma2(acc[5][0], ud, vp0); fma2(acc[5][1], ud, vp1);                   \
                              fma2(acc[5][2], ud, vp2); fma2(acc[5][3], ud, vp3);                   \
        ud = pk2(u1.z, u1.z); fma2(acc[6][0], ud, vp0); fma2(acc[6][1], ud, vp1);                   \
                              fma2(acc[6][2], ud, vp2); fma2(acc[6][3], ud, vp3);                   \
        ud = pk2(u1.w, u1.w); fma2(acc[7][0], ud, vp0); fma2(acc[7][1], ud, vp1);                   \
                              fma2(acc[7][2], ud, vp2); fma2(acc[7][3], ud, vp3);                   \
    }

// ---------------- kernel 0: normalize centroids, zero-pad to 128 rows ----------------
__global__ void __launch_bounds__(256) k_cnorm(const float* __restrict__ cent) {
    int e = blockIdx.x;            // 0..127
    int tid = threadIdx.x;         // 256 threads, 1 float4 each
    float4* dst = (float4*)(g_cnorm + (size_t)e * DD);
    if (e >= NE) { dst[tid] = make_float4(0.f, 0.f, 0.f, 0.f); return; }
    __shared__ float warps[8];
    float4 a = ((const float4*)(cent + (size_t)e * DD))[tid];
    float ss = a.x * a.x + a.y * a.y + a.z * a.z + a.w * a.w;
#pragma unroll
    for (int m = 16; m; m >>= 1) ss += __shfl_xor_sync(0xffffffffu, ss, m);
    if ((tid & 31) == 0) warps[tid >> 5] = ss;
    __syncthreads();
    float tot = 0.f;
#pragma unroll
    for (int w = 0; w < 8; ++w) tot += warps[w];
    float inv = 1.0f / fmaxf(sqrtf(tot), 1e-12f);
    dst[tid] = make_float4(a.x * inv, a.y * inv, a.z * inv, a.w * inv);
}

// ---------------- kernel 1: sim GEMM + softmax + assignment + weight partials ----------------
__global__ void __launch_bounds__(256) k_sim(const float* __restrict__ tokens,
                                             float* __restrict__ aout) {
    __shared__ __align__(16) float As[16][132];   // [k][token m]
    __shared__ __align__(16) float Bs[16][132];   // [k][entity n]
    __shared__ float snorm[128];
    __shared__ float wsum[16][132];

    int tid = threadIdx.x;
    int tx = tid & 15, ty = tid >> 4;
    int blk = blockIdx.x;
    size_t row0 = (size_t)blk << 7;               // 128 tokens per block

    int lm = tid & 127;                           // row within tile
    int lk = (tid >> 7) << 3;                     // k offset: 0 or 8

    const float* Ap = tokens + (row0 + lm) * DD + lk;
    const float* Bp = g_cnorm + (size_t)lm * DD + lk;

    unsigned long long acc[8][4];
#pragma unroll
    for (int i = 0; i < 8; ++i)
#pragma unroll
        for (int p = 0; p < 4; ++p) acc[i][p] = 0ull;

    float ss = 0.f;
    float4 a0 = *(const float4*)Ap;
    float4 a1 = *(const float4*)(Ap + 4);
    float4 b0 = *(const float4*)Bp;
    float4 b1 = *(const float4*)(Bp + 4);

    for (int c = 0; c < 64; ++c) {
        As[lk + 0][lm] = a0.x; As[lk + 1][lm] = a0.y; As[lk + 2][lm] = a0.z; As[lk + 3][lm] = a0.w;
        As[lk + 4][lm] = a1.x; As[lk + 5][lm] = a1.y; As[lk + 6][lm] = a1.z; As[lk + 7][lm] = a1.w;
        Bs[lk + 0][lm] = b0.x; Bs[lk + 1][lm] = b0.y; Bs[lk + 2][lm] = b0.z; Bs[lk + 3][lm] = b0.w;
        Bs[lk + 4][lm] = b1.x; Bs[lk + 5][lm] = b1.y; Bs[lk + 6][lm] = b1.z; Bs[lk + 7][lm] = b1.w;
        ss += a0.x * a0.x + a0.y * a0.y + a0.z * a0.z + a0.w * a0.w
            + a1.x * a1.x + a1.y * a1.y + a1.z * a1.z + a1.w * a1.w;
        __syncthreads();
        if (c < 63) {                              // prefetch next chunk (overlaps INNER16)
            int off = (c + 1) << 4;
            a0 = *(const float4*)(Ap + off);
            a1 = *(const float4*)(Ap + off + 4);
            b0 = *(const float4*)(Bp + off);
            b1 = *(const float4*)(Bp + off + 4);
        }
        INNER16(As, Bs)
        __syncthreads();
    }

    // token sum-of-squares: row lm covered by tid=lm (k 0..7 of each chunk) and tid=lm+128 (k 8..15)
    if (tid < 128) snorm[tid] = ss;
    __syncthreads();
    if (tid >= 128) snorm[tid - 128] += ss;
    __syncthreads();

    bool g1 = (tx < 9);   // second entity group valid only when 64+tx*4+3 < 100
    float pr[8][8];
#pragma unroll
    for (int i = 0; i < 8; ++i) {
        float sc = 10.0f / fmaxf(sqrtf(snorm[ty * 8 + i]), 1e-12f);  // (1/T)/max(||x||,eps)
#pragma unroll
        for (int pp = 0; pp < 4; ++pp) {
            float2 f = upk(acc[i][pp]);
            pr[i][pp * 2 + 0] = f.x * sc;
            pr[i][pp * 2 + 1] = f.y * sc;
        }
    }

    float w0[4] = {0.f, 0.f, 0.f, 0.f}, w1[4] = {0.f, 0.f, 0.f, 0.f};
#pragma unroll
    for (int i = 0; i < 8; ++i) {
        float mx = fmaxf(fmaxf(pr[i][0], pr[i][1]), fmaxf(pr[i][2], pr[i][3]));
        if (g1) mx = fmaxf(mx, fmaxf(fmaxf(pr[i][4], pr[i][5]), fmaxf(pr[i][6], pr[i][7])));
        mx = fmaxf(mx, __shfl_xor_sync(0xffffffffu, mx, 1));
        mx = fmaxf(mx, __shfl_xor_sync(0xffffffffu, mx, 2));
        mx = fmaxf(mx, __shfl_xor_sync(0xffffffffu, mx, 4));
        mx = fmaxf(mx, __shfl_xor_sync(0xffffffffu, mx, 8));
        float sum = 0.f;
#pragma unroll
        for (int n = 0; n < 8; ++n) {
            float t = (n < 4 || g1) ? __expf(pr[i][n] - mx) : 0.f;
            pr[i][n] = t;
            sum += t;
        }
        sum += __shfl_xor_sync(0xffffffffu, sum, 1);
        sum += __shfl_xor_sync(0xffffffffu, sum, 2);
        sum += __shfl_xor_sync(0xffffffffu, sum, 4);
        sum += __shfl_xor_sync(0xffffffffu, sum, 8);
        float inv = 1.0f / sum;
#pragma unroll
        for (int n = 0; n < 8; ++n) pr[i][n] *= inv;

        size_t trow = row0 + (size_t)ty * 8 + i;
        float* rp = aout + trow * NE;
        *(float4*)(rp + tx * 4) = make_float4(pr[i][0], pr[i][1], pr[i][2], pr[i][3]);
        if (g1) *(float4*)(rp + 64 + tx * 4) = make_float4(pr[i][4], pr[i][5], pr[i][6], pr[i][7]);

        float* ap = g_apad + trow * 128;
        *(float4*)(ap + tx * 4) = make_float4(pr[i][0], pr[i][1], pr[i][2], pr[i][3]);
        *(float4*)(ap + 64 + tx * 4) = make_float4(pr[i][4], pr[i][5], pr[i][6], pr[i][7]);

#pragma unroll
        for (int n = 0; n < 4; ++n) { w0[n] += pr[i][n]; w1[n] += pr[i][n + 4]; }
    }

    // per-block entity weight partials
#pragma unroll
    for (int j = 0; j < 4; ++j) {
        wsum[ty][tx * 4 + j] = w0[j];
        wsum[ty][64 + tx * 4 + j] = w1[j];
    }
    __syncthreads();
    if (tid < 128) {
        float s = 0.f;
#pragma unroll
        for (int w = 0; w < 16; ++w) s += wsum[w][tid];
        g_wpart[blk * 128 + tid] = s;
    }
}

// ---------------- kernel 2: weight reduce ----------------
__global__ void __launch_bounds__(1024) k_wred() {
    int tid = threadIdx.x;         // 1024 = 8 batches * 128 entities
    int b = tid >> 7, e = tid & 127;
    float s = 1e-6f;
#pragma unroll
    for (int j = 0; j < 32; ++j) s += g_wpart[(b * 32 + j) * 128 + e];
    g_weights[tid] = s;
}

// ---------------- kernel 3: entity_features GEMM (split-K=4) ----------------
__global__ void __launch_bounds__(256) k_ef(const float* __restrict__ tokens) {
    __shared__ __align__(16) float As[16][132];   // [k][entity]
    __shared__ __align__(16) float Bs[16][132];   // [k][d]

    int tid = threadIdx.x;
    int tx = tid & 15, ty = tid >> 4;
    int bid = blockIdx.x;
    int dt = bid & 7;              // d tile
    int b  = (bid >> 3) & 7;       // batch
    int s  = bid >> 6;             // split 0..3
    size_t tok0 = (size_t)b * 4096 + (size_t)s * 1024;

    int k = tid >> 4;              // 0..15
    int f = tid & 15;
    const float* Apt = g_apad + (tok0 + k) * 128 + f * 4;
    const float* Bpt = tokens + (tok0 + k) * DD + (size_t)dt * 128 + f * 4;

    unsigned long long acc[8][4];
#pragma unroll
    for (int i = 0; i < 8; ++i)
#pragma unroll
        for (int p = 0; p < 4; ++p) acc[i][p] = 0ull;

    float4 a0 = *(const float4*)Apt;
    float4 a1 = *(const float4*)(Apt + 64);
    float4 b0 = *(const float4*)Bpt;
    float4 b1 = *(const float4*)(Bpt + 64);

    for (int c = 0; c < 64; ++c) {
        *(float4*)&As[k][f * 4]      = a0;
        *(float4*)&As[k][f * 4 + 64] = a1;
        *(float4*)&Bs[k][f * 4]      = b0;
        *(float4*)&Bs[k][f * 4 + 64] = b1;
        __syncthreads();
        if (c < 63) {
            size_t offA = (size_t)(c + 1) * 16 * 128;
            size_t offB = (size_t)(c + 1) * 16 * DD;
            a0 = *(const float4*)(Apt + offA);
            a1 = *(const float4*)(Apt + offA + 64);
            b0 = *(const float4*)(Bpt + offB);
            b1 = *(const float4*)(Bpt + offB + 64);
        }
        INNER16(As, Bs)
        __syncthreads();
    }

    float* op = g_efpart + ((size_t)(s * 8 + b) * 128) * DD + (size_t)dt * 128;
#pragma unroll
    for (int i = 0; i < 8; ++i) {
        int e = ty * 8 + i;
        float2 f0 = upk(acc[i][0]), f1 = upk(acc[i][1]);
        float2 f2 = upk(acc[i][2]), f3 = upk(acc[i][3]);
        *(float4*)(op + (size_t)e * DD + tx * 4)      = make_float4(f0.x, f0.y, f1.x, f1.y);
        *(float4*)(op + (size_t)e * DD + 64 + tx * 4) = make_float4(f2.x, f2.y, f3.x, f3.y);
    }
}

// ---------------- kernel 4: combine splits + divide by weights ----------------
__global__ void __launch_bounds__(256) k_combine(float* __restrict__ efout) {
    int gid = blockIdx.x * 256 + threadIdx.x;     // float4 index, 0..204799
    int d4 = gid & 255;
    int be = gid >> 8;                            // b*100 + e
    int e = be % 100;
    int b = be / 100;
    const float4* p = (const float4*)g_efpart;
    size_t idx = ((size_t)b * 128 + e) * 256 + d4;
    size_t sstr = (size_t)8 * 128 * 256;
    float4 v = p[idx];
    float4 t;
    t = p[idx + sstr];     v.x += t.x; v.y += t.y; v.z += t.z; v.w += t.w;
    t = p[idx + 2 * sstr]; v.x += t.x; v.y += t.y; v.z += t.z; v.w += t.w;
    t = p[idx + 3 * sstr]; v.x += t.x; v.y += t.y; v.z += t.z; v.w += t.w;
    float inv = 1.0f / g_weights[b * 128 + e];
    ((float4*)efout)[gid] = make_float4(v.x * inv, v.y * inv, v.z * inv, v.w * inv);
}

extern "C" void kernel_launch(void* const* d_in, const int* in_sizes, int n_in,
                              void* d_out, int out_size) {
    const float* tokens = (const float*)d_in[0];   // (8,4096,1024)
    const float* cent   = (const float*)d_in[1];   // (100,1024)
    float* out = (float*)d_out;                    // assignment | entity_features

    k_cnorm<<<128, 256>>>(cent);
    k_sim<<<256, 256>>>(tokens, out);
    k_wred<<<1, 1024>>>();
    k_ef<<<256, 256>>>(tokens);
    k_combine<<<800, 256>>>(out + (size_t)BT * NE);
}

// round 5
// speedup vs baseline: 1.7377x; 1.7377x over previous
#include <cuda_runtime.h>
#include <cuda_bf16.h>
#include <math.h>
#include <stdint.h>

#define DD 1024
#define NE 100
#define BT 32768   // 8*4096

// ---------------- device scratch ----------------
__device__ __nv_bfloat16 g_cn_hi[128 * DD];         // normalized centroids bf16 hi (padded)
__device__ __nv_bfloat16 g_cn_lo[128 * DD];         // normalized centroids bf16 lo
__device__ __nv_bfloat16 g_ah[(size_t)128 * BT];    // assignment^T bf16 hi [e][t]
__device__ __nv_bfloat16 g_al[(size_t)128 * BT];    // assignment^T bf16 lo [e][t]
__device__ float g_wpart[256 * 128];                // per-block weight partials
__device__ float g_weights[8 * 128];                // sum over T + 1e-6
__device__ float g_efpart[(size_t)4 * 8 * 128 * DD]; // split-K partials

// ---------------- helpers ----------------
__device__ __forceinline__ uint32_t smem_u32(const void* p) {
    uint32_t a;
    asm("{ .reg .u64 t; cvta.to.shared.u64 t, %1; cvt.u32.u64 %0, t; }" : "=r"(a) : "l"(p));
    return a;
}
__device__ __forceinline__ uint32_t sw128(uint32_t off) {
    return off ^ ((off >> 3) & 0x70u);
}
__device__ __forceinline__ uint32_t pk_bf16(float lo, float hi) {
    uint32_t r;
    asm("cvt.rn.bf16x2.f32 %0, %1, %2;" : "=r"(r) : "f"(hi), "f"(lo));
    return r;
}
__device__ __forceinline__ void sts64(uint32_t addr, uint32_t a, uint32_t b) {
    asm volatile("st.shared.v2.b32 [%0], {%1, %2};" :: "r"(addr), "r"(a), "r"(b) : "memory");
}
__device__ __forceinline__ void sts128(uint32_t addr, uint4 v) {
    asm volatile("st.shared.v4.b32 [%0], {%1, %2, %3, %4};"
                 :: "r"(addr), "r"(v.x), "r"(v.y), "r"(v.z), "r"(v.w) : "memory");
}
__device__ __forceinline__ void ldm4(uint32_t addr, uint32_t* r) {
    asm volatile("ldmatrix.sync.aligned.m8n8.x4.shared.b16 {%0,%1,%2,%3}, [%4];"
                 : "=r"(r[0]), "=r"(r[1]), "=r"(r[2]), "=r"(r[3]) : "r"(addr));
}
__device__ __forceinline__ void ldm4t(uint32_t addr, uint32_t* r) {
    asm volatile("ldmatrix.sync.aligned.m8n8.x4.trans.shared.b16 {%0,%1,%2,%3}, [%4];"
                 : "=r"(r[0]), "=r"(r[1]), "=r"(r[2]), "=r"(r[3]) : "r"(addr));
}
__device__ __forceinline__ void mmabf(float* c, const uint32_t* a, uint32_t b0, uint32_t b1) {
    asm volatile("mma.sync.aligned.m16n8k16.row.col.f32.bf16.bf16.f32 "
                 "{%0,%1,%2,%3}, {%4,%5,%6,%7}, {%8,%9}, {%0,%1,%2,%3};"
                 : "+f"(c[0]), "+f"(c[1]), "+f"(c[2]), "+f"(c[3])
                 : "r"(a[0]), "r"(a[1]), "r"(a[2]), "r"(a[3]), "r"(b0), "r"(b1));
}

// ---------------- kernel 0: normalize centroids -> bf16 hi/lo, zero-pad ----------------
__global__ void __launch_bounds__(256) k_cnorm(const float* __restrict__ cent) {
    int e = blockIdx.x;            // 0..127
    int tid = threadIdx.x;
    uint2* dh = (uint2*)(g_cn_hi + (size_t)e * DD);
    uint2* dl = (uint2*)(g_cn_lo + (size_t)e * DD);
    if (e >= NE) { dh[tid] = make_uint2(0u, 0u); dl[tid] = make_uint2(0u, 0u); return; }
    __shared__ float warps[8];
    float4 a = ((const float4*)(cent + (size_t)e * DD))[tid];
    float ss = a.x * a.x + a.y * a.y + a.z * a.z + a.w * a.w;
#pragma unroll
    for (int m = 16; m; m >>= 1) ss += __shfl_xor_sync(0xffffffffu, ss, m);
    if ((tid & 31) == 0) warps[tid >> 5] = ss;
    __syncthreads();
    float tot = 0.f;
#pragma unroll
    for (int w = 0; w < 8; ++w) tot += warps[w];
    float inv = 1.0f / fmaxf(sqrtf(tot), 1e-12f);
    float4 v = make_float4(a.x * inv, a.y * inv, a.z * inv, a.w * inv);
    float h0 = __bfloat162float(__float2bfloat16_rn(v.x));
    float h1 = __bfloat162float(__float2bfloat16_rn(v.y));
    float h2 = __bfloat162float(__float2bfloat16_rn(v.z));
    float h3 = __bfloat162float(__float2bfloat16_rn(v.w));
    dh[tid] = make_uint2(pk_bf16(h0, h1), pk_bf16(h2, h3));
    dl[tid] = make_uint2(pk_bf16(v.x - h0, v.y - h1), pk_bf16(v.z - h2, v.w - h3));
}

// ---------------- kernel 1: sim GEMM (HMMA, hi/lo split) + softmax + asg^T + weights ----
// Tile 128 tokens x 128 entities, K=1024 in 16 chunks of 64, double-buffered smem.
#define SIM_SMEM (1024 + 1024 + 2 * 65536)

__global__ void __launch_bounds__(256, 1) k_sim(const float* __restrict__ tokens,
                                                float* __restrict__ aout) {
    extern __shared__ char dsm[];
    uint32_t raw = smem_u32(dsm);
    uint32_t base = (raw + 1023u) & ~1023u;
    char* cbase = dsm + (base - raw);
    float* snorm = (float*)cbase;              // 128 f32
    float* stage = (float*)(cbase + 1024);     // epilogue staging, pitch 130
    uint32_t tiles = base + 1024u;

    int tid = threadIdx.x;
    int lane = tid & 31, w = tid >> 5;
    int wm = w & 3, wn = w >> 2;
    int m0 = wm * 32, n0 = wn * 64;
    size_t row0 = (size_t)blockIdx.x << 7;

    const int ty16 = tid >> 4, tx = tid & 15;
    const int brow = tid >> 3, q = tid & 7;
    const float* Abase = tokens + row0 * DD;

    float acc[2][8][4];
#pragma unroll
    for (int i = 0; i < 2; ++i)
#pragma unroll
        for (int j = 0; j < 8; ++j)
#pragma unroll
            for (int p = 0; p < 4; ++p) acc[i][j][p] = 0.f;
    float ss[8];
#pragma unroll
    for (int g = 0; g < 8; ++g) ss[g] = 0.f;

    float4 pa[8];
#pragma unroll
    for (int g = 0; g < 8; ++g)
        pa[g] = *(const float4*)(Abase + (size_t)(g * 16 + ty16) * DD + tx * 4);

    for (int c = 0; c < 16; ++c) {
        uint32_t tb = tiles + (uint32_t)(c & 1) * 65536u;
        uint32_t tAh = tb, tAl = tb + 16384u, tBh = tb + 32768u, tBl = tb + 49152u;

        // B: centroids bf16 hi/lo (L2-resident)
#pragma unroll
        for (int p = 0; p < 4; ++p) {
            int r = p * 32 + brow;
            uint32_t off = sw128((uint32_t)(r * 128 + q * 16));
            uint4 vh = *(const uint4*)(g_cn_hi + (size_t)r * DD + c * 64 + q * 8);
            uint4 vl = *(const uint4*)(g_cn_lo + (size_t)r * DD + c * 64 + q * 8);
            sts128(tBh + off, vh);
            sts128(tBl + off, vl);
        }
        // A: tokens fp32 -> bf16 hi/lo (+ norm accumulation)
#pragma unroll
        for (int g = 0; g < 8; ++g) {
            float4 a = pa[g];
            ss[g] += a.x * a.x + a.y * a.y + a.z * a.z + a.w * a.w;
            float h0 = __bfloat162float(__float2bfloat16_rn(a.x));
            float h1 = __bfloat162float(__float2bfloat16_rn(a.y));
            float h2 = __bfloat162float(__float2bfloat16_rn(a.z));
            float h3 = __bfloat162float(__float2bfloat16_rn(a.w));
            uint32_t off = sw128((uint32_t)((g * 16 + ty16) * 128 + tx * 8));
            sts64(tAh + off, pk_bf16(h0, h1), pk_bf16(h2, h3));
            sts64(tAl + off, pk_bf16(a.x - h0, a.y - h1), pk_bf16(a.z - h2, a.w - h3));
        }
        __syncthreads();
        if (c < 15) {
#pragma unroll
            for (int g = 0; g < 8; ++g)
                pa[g] = *(const float4*)(Abase + (size_t)(g * 16 + ty16) * DD + (c + 1) * 64 + tx * 4);
        }

        uint32_t koff = (uint32_t)((lane >> 4) & 1) * 16u;
#pragma unroll
        for (int ks = 0; ks < 4; ++ks) {
            uint32_t kb = (uint32_t)ks * 32u;
            uint32_t ah[2][4], al[2][4];
#pragma unroll
            for (int mt = 0; mt < 2; ++mt) {
                uint32_t off = sw128((uint32_t)((m0 + mt * 16 + (lane & 15)) * 128) + kb + koff);
                ldm4(tAh + off, ah[mt]);
                ldm4(tAl + off, al[mt]);
            }
#pragma unroll
            for (int np = 0; np < 4; ++np) {
                uint32_t boff = sw128((uint32_t)((n0 + np * 16 + (lane & 15)) * 128) + kb + koff);
                uint32_t bh[4], bl[4];
                ldm4(tBh + boff, bh);
                ldm4(tBl + boff, bl);
#pragma unroll
                for (int mt = 0; mt < 2; ++mt) {
                    mmabf(acc[mt][np * 2],     ah[mt], bh[0], bh[2]);
                    mmabf(acc[mt][np * 2],     ah[mt], bl[0], bl[2]);
                    mmabf(acc[mt][np * 2],     al[mt], bh[0], bh[2]);
                    mmabf(acc[mt][np * 2 + 1], ah[mt], bh[1], bh[3]);
                    mmabf(acc[mt][np * 2 + 1], ah[mt], bl[1], bl[3]);
                    mmabf(acc[mt][np * 2 + 1], al[mt], bh[1], bh[3]);
                }
            }
        }
    }

    // token norms
#pragma unroll
    for (int g = 0; g < 8; ++g) {
        float s = ss[g];
        s += __shfl_xor_sync(0xffffffffu, s, 1);
        s += __shfl_xor_sync(0xffffffffu, s, 2);
        s += __shfl_xor_sync(0xffffffffu, s, 4);
        s += __shfl_xor_sync(0xffffffffu, s, 8);
        if (tx == 0) snorm[g * 16 + ty16] = s;
    }
    __syncthreads();   // all ldmatrix done before staging overwrites buffers

    // stage sim tile to smem (pitch 130)
#pragma unroll
    for (int mt = 0; mt < 2; ++mt)
#pragma unroll
        for (int nt = 0; nt < 8; ++nt) {
            int r = m0 + mt * 16 + (lane >> 2);
            int col = n0 + nt * 8 + (lane & 3) * 2;
            *(float2*)&stage[r * 130 + col] = make_float2(acc[mt][nt][0], acc[mt][nt][1]);
            *(float2*)&stage[(r + 8) * 130 + col] = make_float2(acc[mt][nt][2], acc[mt][nt][3]);
        }
    __syncthreads();

    if (tid < 128) {
        float v[128];
#pragma unroll
        for (int j = 0; j < 128; ++j) v[j] = stage[tid * 130 + j];
        float sc = 10.0f / fmaxf(sqrtf(snorm[tid]), 1e-12f);  // (1/T)/max(||x||,eps)
        float mx = -1e30f;
#pragma unroll
        for (int j = 0; j < NE; ++j) { v[j] *= sc; mx = fmaxf(mx, v[j]); }
        float sum = 0.f;
#pragma unroll
        for (int j = 0; j < 128; ++j) {
            float t = (j < NE) ? __expf(v[j] - mx) : 0.f;
            v[j] = t;
            sum += t;
        }
        float inv = 1.0f / sum;
#pragma unroll
        for (int j = 0; j < 128; ++j) v[j] *= inv;

        size_t trow = row0 + tid;
        float* rp = aout + trow * NE;
#pragma unroll
        for (int j = 0; j < 25; ++j)
            *(float4*)(rp + j * 4) = make_float4(v[j * 4], v[j * 4 + 1], v[j * 4 + 2], v[j * 4 + 3]);
        // assignment^T bf16 hi/lo for GEMM2
#pragma unroll
        for (int e = 0; e < 128; ++e) {
            __nv_bfloat16 hb = __float2bfloat16_rn(v[e]);
            g_ah[(size_t)e * BT + trow] = hb;
            g_al[(size_t)e * BT + trow] = __float2bfloat16_rn(v[e] - __bfloat162float(hb));
        }
        // write back for weight column sums
#pragma unroll
        for (int j = 0; j < 128; ++j) stage[tid * 130 + j] = v[j];
    }
    __syncthreads();
    if (tid < 128) {
        float s = 0.f;
#pragma unroll
        for (int r = 0; r < 128; ++r) s += stage[r * 130 + tid];
        g_wpart[blockIdx.x * 128 + tid] = s;
    }
}

// ---------------- kernel 2: weight reduce ----------------
__global__ void __launch_bounds__(1024) k_wred() {
    int tid = threadIdx.x;
    int b = tid >> 7, e = tid & 127;
    float s = 1e-6f;
#pragma unroll
    for (int j = 0; j < 32; ++j) s += g_wpart[(b * 32 + j) * 128 + e];
    g_weights[tid] = s;
}

// ---------------- kernel 3: entity_features GEMM (HMMA, split-K=4) ----------------
// Tile 128 entities x 128 d, K=1024 tokens per CTA (16 chunks of 64).
#define EF_SMEM (1024 + 2 * 65536)

__global__ void __launch_bounds__(256, 1) k_ef(const float* __restrict__ tokens) {
    extern __shared__ char dsm[];
    uint32_t raw = smem_u32(dsm);
    uint32_t tiles = (raw + 1023u) & ~1023u;

    int tid = threadIdx.x;
    int lane = tid & 31, w = tid >> 5;
    int wm = w & 3, wn = w >> 2;
    int m0 = wm * 32, n0 = wn * 64;

    int bid = blockIdx.x;
    int dt = bid & 7;
    int b  = (bid >> 3) & 7;
    int s  = bid >> 6;
    size_t tok0 = (size_t)b * 4096 + (size_t)s * 1024;

    const int ty16 = tid >> 4, tx = tid & 15;
    const int brow = tid >> 3, q = tid & 7;

    float acc[2][8][4];
#pragma unroll
    for (int i = 0; i < 2; ++i)
#pragma unroll
        for (int j = 0; j < 8; ++j)
#pragma unroll
            for (int p = 0; p < 4; ++p) acc[i][j][p] = 0.f;

    float4 pb[8];
#pragma unroll
    for (int g = 0; g < 4; ++g)
#pragma unroll
        for (int sub = 0; sub < 2; ++sub)
            pb[g * 2 + sub] = *(const float4*)(tokens + (tok0 + g * 16 + ty16) * DD +
                                               dt * 128 + sub * 64 + tx * 4);

    for (int c = 0; c < 16; ++c) {
        uint32_t tb = tiles + (uint32_t)(c & 1) * 65536u;
        uint32_t tAh = tb, tAl = tb + 16384u, tBh = tb + 32768u, tBl = tb + 49152u;

        // A: assignment^T bf16 hi/lo [e][t]
#pragma unroll
        for (int p = 0; p < 4; ++p) {
            int r = p * 32 + brow;
            uint32_t off = sw128((uint32_t)(r * 128 + q * 16));
            uint4 vh = *(const uint4*)(g_ah + (size_t)r * BT + tok0 + c * 64 + q * 8);
            uint4 vl = *(const uint4*)(g_al + (size_t)r * BT + tok0 + c * 64 + q * 8);
            sts128(tAh + off, vh);
            sts128(tAl + off, vl);
        }
        // B: tokens fp32 -> bf16 hi/lo, two 64x64 subtiles [k][d]
#pragma unroll
        for (int g = 0; g < 4; ++g)
#pragma unroll
            for (int sub = 0; sub < 2; ++sub) {
                float4 a = pb[g * 2 + sub];
                float h0 = __bfloat162float(__float2bfloat16_rn(a.x));
                float h1 = __bfloat162float(__float2bfloat16_rn(a.y));
                float h2 = __bfloat162float(__float2bfloat16_rn(a.z));
                float h3 = __bfloat162float(__float2bfloat16_rn(a.w));
                uint32_t off = (uint32_t)sub * 8192u +
                               sw128((uint32_t)((g * 16 + ty16) * 128 + tx * 8));
                sts64(tBh + off, pk_bf16(h0, h1), pk_bf16(h2, h3));
                sts64(tBl + off, pk_bf16(a.x - h0, a.y - h1), pk_bf16(a.z - h2, a.w - h3));
            }
        __syncthreads();
        if (c < 15) {
#pragma unroll
            for (int g = 0; g < 4; ++g)
#pragma unroll
                for (int sub = 0; sub < 2; ++sub)
                    pb[g * 2 + sub] = *(const float4*)(tokens + (tok0 + (c + 1) * 64 + g * 16 + ty16) * DD +
                                                       dt * 128 + sub * 64 + tx * 4);
        }

        uint32_t koffA = (uint32_t)((lane >> 4) & 1) * 16u;
        uint32_t krow = (uint32_t)((lane & 7) + ((lane >> 4) & 1) * 8);
        uint32_t dh16 = (uint32_t)((lane >> 3) & 1) * 16u;
        uint32_t bsub = (uint32_t)wn * 8192u;
#pragma unroll
        for (int ks = 0; ks < 4; ++ks) {
            uint32_t kb = (uint32_t)ks * 32u;
            uint32_t ah[2][4], al[2][4];
#pragma unroll
            for (int mt = 0; mt < 2; ++mt) {
                uint32_t off = sw128((uint32_t)((m0 + mt * 16 + (lane & 15)) * 128) + kb + koffA);
                ldm4(tAh + off, ah[mt]);
                ldm4(tAl + off, al[mt]);
            }
#pragma unroll
            for (int np = 0; np < 4; ++np) {
                uint32_t boff = bsub + sw128((uint32_t)((ks * 16 + krow) * 128 + np * 32) + dh16);
                uint32_t bh[4], bl[4];
                ldm4t(tBh + boff, bh);
                ldm4t(tBl + boff, bl);
#pragma unroll
                for (int mt = 0; mt < 2; ++mt) {
                    mmabf(acc[mt][np * 2],     ah[mt], bh[0], bh[2]);
                    mmabf(acc[mt][np * 2],     ah[mt], bl[0], bl[2]);
                    mmabf(acc[mt][np * 2],     al[mt], bh[0], bh[2]);
                    mmabf(acc[mt][np * 2 + 1], ah[mt], bh[1], bh[3]);
                    mmabf(acc[mt][np * 2 + 1], ah[mt], bl[1], bl[3]);
                    mmabf(acc[mt][np * 2 + 1], al[mt], bh[1], bh[3]);
                }
            }
        }
    }

    float* ob = g_efpart + ((size_t)(s * 8 + b) * 128) * DD + (size_t)dt * 128;
#pragma unroll
    for (int mt = 0; mt < 2; ++mt)
#pragma unroll
        for (int nt = 0; nt < 8; ++nt) {
            int e = m0 + mt * 16 + (lane >> 2);
            int d = n0 + nt * 8 + (lane & 3) * 2;
            *(float2*)(ob + (size_t)e * DD + d) = make_float2(acc[mt][nt][0], acc[mt][nt][1]);
            *(float2*)(ob + (size_t)(e + 8) * DD + d) = make_float2(acc[mt][nt][2], acc[mt][nt][3]);
        }
}

// ---------------- kernel 4: combine splits + divide by weights ----------------
__global__ void __launch_bounds__(256) k_combine(float* __restrict__ efout) {
    int gid = blockIdx.x * 256 + threadIdx.x;
    int d4 = gid & 255;
    int be = gid >> 8;
    int e = be % 100;
    int b = be / 100;
    const float4* p = (const float4*)g_efpart;
    size_t idx = ((size_t)b * 128 + e) * 256 + d4;
    size_t sstr = (size_t)8 * 128 * 256;
    float4 v = p[idx];
    float4 t;
    t = p[idx + sstr];     v.x += t.x; v.y += t.y; v.z += t.z; v.w += t.w;
    t = p[idx + 2 * sstr]; v.x += t.x; v.y += t.y; v.z += t.z; v.w += t.w;
    t = p[idx + 3 * sstr]; v.x += t.x; v.y += t.y; v.z += t.z; v.w += t.w;
    float inv = 1.0f / g_weights[b * 128 + e];
    ((float4*)efout)[gid] = make_float4(v.x * inv, v.y * inv, v.z * inv, v.w * inv);
}

extern "C" void kernel_launch(void* const* d_in, const int* in_sizes, int n_in,
                              void* d_out, int out_size) {
    const float* tokens = (const float*)d_in[0];   // (8,4096,1024)
    const float* cent   = (const float*)d_in[1];   // (100,1024)
    float* out = (float*)d_out;                    // assignment | entity_features

    cudaFuncSetAttribute(k_sim, cudaFuncAttributeMaxDynamicSharedMemorySize, SIM_SMEM);
    cudaFuncSetAttribute(k_ef,  cudaFuncAttributeMaxDynamicSharedMemorySize, EF_SMEM);

    k_cnorm<<<128, 256>>>(cent);
    k_sim<<<256, 256, SIM_SMEM>>>(tokens, out);
    k_wred<<<1, 1024>>>();
    k_ef<<<256, 256, EF_SMEM>>>(tokens);
    k_combine<<<800, 256>>>(out + (size_t)BT * NE);
}